// round 1
// baseline (speedup 1.0000x reference)
#include <cuda_runtime.h>
#include <cuda_bf16.h>

// Problem constants
#define HH 768
#define NN 64
#define LSEQ 2048
#define BB 4
#define NUNITS (BB * HH)            // 3072 (b,h) units
#define THREADS_PER_UNIT 16         // each thread owns 4 modes (2 f32x2 pairs)
#define UNITS_PER_BLOCK 4
#define BLOCK_THREADS (THREADS_PER_UNIT * UNITS_PER_BLOCK)  // 64
#define NBLOCKS (NUNITS / UNITS_PER_BLOCK)                   // 768
#define TILE 128                    // timesteps per shared-mem tile
#define NTILES (LSEQ / TILE)        // 16

// Precomputed per-(h,n) discretized parameters (float4 for aligned vector loads)
__device__ float4 g_Are4[HH * NN / 4];
__device__ float4 g_Aim4[HH * NN / 4];
__device__ float4 g_Bre4[HH * NN / 4];
__device__ float4 g_Bim4[HH * NN / 4];

// ---------------- f32x2 helpers (sm_103a packed fp32) ----------------
__device__ __forceinline__ unsigned long long pk2(float lo, float hi) {
    unsigned long long r;
    asm("mov.b64 %0, {%1, %2};" : "=l"(r) : "f"(lo), "f"(hi));
    return r;
}
__device__ __forceinline__ void upk2(unsigned long long v, float& lo, float& hi) {
    asm("mov.b64 {%0, %1}, %2;" : "=f"(lo), "=f"(hi) : "l"(v));
}
__device__ __forceinline__ unsigned long long f2fma(unsigned long long a,
                                                    unsigned long long b,
                                                    unsigned long long c) {
    unsigned long long d;
    asm("fma.rn.f32x2 %0, %1, %2, %3;" : "=l"(d) : "l"(a), "l"(b), "l"(c));
    return d;
}
__device__ __forceinline__ unsigned long long f2mul(unsigned long long a,
                                                    unsigned long long b) {
    unsigned long long d;
    asm("mul.rn.f32x2 %0, %1, %2;" : "=l"(d) : "l"(a), "l"(b));
    return d;
}

// ---------------- Kernel 0: ZOH discretization (tiny) ----------------
__global__ void setup_kernel(const float* __restrict__ log_neg_real,
                             const float* __restrict__ imag,
                             const float* __restrict__ B_re,
                             const float* __restrict__ B_im,
                             const float* __restrict__ log_dt) {
    int idx = blockIdx.x * blockDim.x + threadIdx.x;
    if (idx >= HH * NN) return;
    int h = idx >> 6;

    float lre = -expf(log_neg_real[idx]);
    float lim = imag[idx];
    float dt  = expf(log_dt[h]);

    // A_bar = exp(lambda * dt)
    float zre = lre * dt, zim = lim * dt;
    float ea = expf(zre);
    float sn, cs;
    sincosf(zim, &sn, &cs);
    float Are = ea * cs, Aim = ea * sn;

    // B_bar = (A_bar - 1) / lambda * (B_re + i B_im)
    float dre = Are - 1.0f, dim = Aim;
    float den = lre * lre + lim * lim;
    float ire = lre / den, iim = -lim / den;
    float tre = dre * ire - dim * iim;
    float tim = dre * iim + dim * ire;
    float br = B_re[idx], bi = B_im[idx];
    float Bbre = tre * br - tim * bi;
    float Bbim = tre * bi + tim * br;

    ((float*)g_Are4)[idx] = Are;
    ((float*)g_Aim4)[idx] = Aim;
    ((float*)g_Bre4)[idx] = Bbre;
    ((float*)g_Bim4)[idx] = Bbim;
}

// ---------------- Kernel 1: recurrence over L, packed f32x2 ----------------
__global__ void __launch_bounds__(BLOCK_THREADS)
ssm_scan_kernel(const float* __restrict__ u,
                const float* __restrict__ C_re,
                const float* __restrict__ C_im,
                const float* __restrict__ Dv,
                float* __restrict__ y) {
    __shared__ float4 u_sh[UNITS_PER_BLOCK][TILE / 4];
    __shared__ float4 y_sh[UNITS_PER_BLOCK][TILE / 4];

    const int tid  = threadIdx.x;
    const int unit = tid >> 4;          // 0..3
    const int s    = tid & 15;          // lane within unit, owns n = 4s..4s+3
    const int ug   = blockIdx.x * UNITS_PER_BLOCK + unit;   // (b,h) flat
    const int h    = ug % HH;

    // Parameter loads (float4 = modes 4s..4s+3)
    const int p4 = h * (NN / 4) + s;
    float4 av = g_Are4[p4];
    float4 iv = g_Aim4[p4];
    float4 bv = g_Bre4[p4];
    float4 jv = g_Bim4[p4];
    float4 cv = ((const float4*)C_re)[p4];
    float4 dv = ((const float4*)C_im)[p4];

    unsigned long long aRe0 = pk2(av.x, av.y), aRe1 = pk2(av.z, av.w);
    unsigned long long aIm0 = pk2(iv.x, iv.y), aIm1 = pk2(iv.z, iv.w);
    unsigned long long nIm0 = pk2(-iv.x, -iv.y), nIm1 = pk2(-iv.z, -iv.w);
    unsigned long long bRe0 = pk2(bv.x, bv.y), bRe1 = pk2(bv.z, bv.w);
    unsigned long long bIm0 = pk2(jv.x, jv.y), bIm1 = pk2(jv.z, jv.w);
    unsigned long long cRe0 = pk2(cv.x, cv.y), cRe1 = pk2(cv.z, cv.w);
    unsigned long long nCi0 = pk2(-dv.x, -dv.y), nCi1 = pk2(-dv.z, -dv.w);

    unsigned long long xre0 = 0ull, xim0 = 0ull, xre1 = 0ull, xim1 = 0ull;
    const float Dh = Dv[h];

    const float4* u4 = (const float4*)u;
    float4*       y4 = (float4*)y;
    const size_t rowbase = (size_t)blockIdx.x * UNITS_PER_BLOCK;

    for (int tt = 0; tt < NTILES; ++tt) {
        __syncthreads();
        // cooperative coalesced load of 4 rows x 128 timesteps
        #pragma unroll
        for (int i = tid; i < UNITS_PER_BLOCK * (TILE / 4); i += BLOCK_THREADS) {
            int row = i >> 5, col = i & 31;
            u_sh[row][col] = u4[(rowbase + row) * (LSEQ / 4) + tt * (TILE / 4) + col];
        }
        __syncthreads();

        #pragma unroll 1
        for (int t4 = 0; t4 < TILE / 4; ++t4) {
            float4 uu = u_sh[unit][t4];
            float* ysr = (float*)&y_sh[unit][0];
            #pragma unroll
            for (int j = 0; j < 4; ++j) {
                float us = (j == 0) ? uu.x : (j == 1) ? uu.y : (j == 2) ? uu.z : uu.w;
                unsigned long long uu2 = pk2(us, us);

                // x' = A*x + Bbar*u   (complex, two packed mode-pairs)
                unsigned long long r0 = f2fma(nIm0, xim0, f2mul(bRe0, uu2));
                unsigned long long i0 = f2fma(aRe0, xim0, f2mul(bIm0, uu2));
                unsigned long long r1 = f2fma(nIm1, xim1, f2mul(bRe1, uu2));
                unsigned long long i1 = f2fma(aRe1, xim1, f2mul(bIm1, uu2));
                r0 = f2fma(aRe0, xre0, r0);
                i0 = f2fma(aIm0, xre0, i0);
                r1 = f2fma(aRe1, xre1, r1);
                i1 = f2fma(aIm1, xre1, i1);
                xre0 = r0; xim0 = i0; xre1 = r1; xim1 = i1;

                // partial Re(C . x) over this thread's 4 modes
                unsigned long long pp = f2mul(cRe0, xre0);
                pp = f2fma(nCi0, xim0, pp);
                pp = f2fma(cRe1, xre1, pp);
                pp = f2fma(nCi1, xim1, pp);
                float plo, phi;
                upk2(pp, plo, phi);
                float p = plo + phi;

                // reduce across the 16 threads of the unit
                p += __shfl_down_sync(0xFFFFFFFFu, p, 8, 16);
                p += __shfl_down_sync(0xFFFFFFFFu, p, 4, 16);
                p += __shfl_down_sync(0xFFFFFFFFu, p, 2, 16);
                p += __shfl_down_sync(0xFFFFFFFFu, p, 1, 16);
                if (s == 0) ysr[t4 * 4 + j] = fmaf(Dh, us, p);
            }
        }
        __syncthreads();
        // coalesced store of the 4x128 output tile
        #pragma unroll
        for (int i = tid; i < UNITS_PER_BLOCK * (TILE / 4); i += BLOCK_THREADS) {
            int row = i >> 5, col = i & 31;
            y4[(rowbase + row) * (LSEQ / 4) + tt * (TILE / 4) + col] = y_sh[row][col];
        }
    }
}

extern "C" void kernel_launch(void* const* d_in, const int* in_sizes, int n_in,
                              void* d_out, int out_size) {
    const float* u    = (const float*)d_in[0];
    const float* lnr  = (const float*)d_in[1];
    const float* im   = (const float*)d_in[2];
    const float* B_re = (const float*)d_in[3];
    const float* B_im = (const float*)d_in[4];
    const float* C_re = (const float*)d_in[5];
    const float* C_im = (const float*)d_in[6];
    const float* ldt  = (const float*)d_in[7];
    const float* Dv   = (const float*)d_in[8];
    float* y = (float*)d_out;

    setup_kernel<<<(HH * NN + 255) / 256, 256>>>(lnr, im, B_re, B_im, ldt);
    ssm_scan_kernel<<<NBLOCKS, BLOCK_THREADS>>>(u, C_re, C_im, Dv, y);
}

// round 2
// speedup vs baseline: 1.4048x; 1.4048x over previous
#include <cuda_runtime.h>
#include <cuda_bf16.h>

// Problem constants
#define HH 768
#define NN 64
#define LSEQ 2048
#define BB 4
#define NUNITS (BB * HH)            // 3072 (b,h) units
#define TPU 16                      // threads per unit; each owns 4 modes (2 f32x2 pairs)
#define UPB 2                       // units per block
#define BLOCK_THREADS (TPU * UPB)   // 32
#define NBLOCKS (NUNITS / UPB)      // 1536
#define TILE 64                     // timesteps per smem tile
#define NTILES (LSEQ / TILE)        // 32

// Precomputed per-(h,n): A_bar and K = C * B_bar (C folded in)
__device__ float4 g_Are4[HH * NN / 4];
__device__ float4 g_Aim4[HH * NN / 4];
__device__ float4 g_Kre4[HH * NN / 4];
__device__ float4 g_Kim4[HH * NN / 4];

// ---------------- f32x2 helpers (sm_103a packed fp32) ----------------
typedef unsigned long long ull;
__device__ __forceinline__ ull pk2(float lo, float hi) {
    ull r; asm("mov.b64 %0, {%1, %2};" : "=l"(r) : "f"(lo), "f"(hi)); return r;
}
__device__ __forceinline__ void upk2(ull v, float& lo, float& hi) {
    asm("mov.b64 {%0, %1}, %2;" : "=f"(lo), "=f"(hi) : "l"(v));
}
__device__ __forceinline__ ull f2fma(ull a, ull b, ull c) {
    ull d; asm("fma.rn.f32x2 %0, %1, %2, %3;" : "=l"(d) : "l"(a), "l"(b), "l"(c)); return d;
}
__device__ __forceinline__ ull f2mul(ull a, ull b) {
    ull d; asm("mul.rn.f32x2 %0, %1, %2;" : "=l"(d) : "l"(a), "l"(b)); return d;
}
__device__ __forceinline__ ull f2add(ull a, ull b) {
    ull d; asm("add.rn.f32x2 %0, %1, %2;" : "=l"(d) : "l"(a), "l"(b)); return d;
}

// ---------------- Kernel 0: ZOH discretization + fold C (tiny) ----------------
__global__ void setup_kernel(const float* __restrict__ log_neg_real,
                             const float* __restrict__ imag,
                             const float* __restrict__ B_re,
                             const float* __restrict__ B_im,
                             const float* __restrict__ C_re,
                             const float* __restrict__ C_im,
                             const float* __restrict__ log_dt) {
    int idx = blockIdx.x * blockDim.x + threadIdx.x;
    if (idx >= HH * NN) return;
    int h = idx >> 6;

    float lre = -expf(log_neg_real[idx]);
    float lim = imag[idx];
    float dt  = expf(log_dt[h]);

    // A_bar = exp(lambda * dt)
    float zre = lre * dt, zim = lim * dt;
    float ea = expf(zre);
    float sn, cs; sincosf(zim, &sn, &cs);
    float Are = ea * cs, Aim = ea * sn;

    // B_bar = (A_bar - 1) / lambda * (B_re + i B_im)
    float dre = Are - 1.0f, dim = Aim;
    float den = lre * lre + lim * lim;
    float ire = lre / den, iim = -lim / den;
    float tre = dre * ire - dim * iim;
    float tim = dre * iim + dim * ire;
    float br = B_re[idx], bi = B_im[idx];
    float Bbre = tre * br - tim * bi;
    float Bbim = tre * bi + tim * br;

    // K = C * B_bar  (fold C into the input coefficient)
    float cr = C_re[idx], ci = C_im[idx];
    float Kre = cr * Bbre - ci * Bbim;
    float Kim = cr * Bbim + ci * Bbre;

    ((float*)g_Are4)[idx] = Are;
    ((float*)g_Aim4)[idx] = Aim;
    ((float*)g_Kre4)[idx] = Kre;
    ((float*)g_Kim4)[idx] = Kim;
}

// ---------------- Kernel 1: recurrence over L, packed f32x2, deferred reduce ----------------
__global__ void __launch_bounds__(BLOCK_THREADS)
ssm_scan_kernel(const float* __restrict__ u,
                const float* __restrict__ Dv,
                float* __restrict__ y) {
    __shared__ float4 u_sh[UPB][TILE / 4];
    __shared__ ull    pp_sh[UPB][TILE][17];   // padded stride: conflict-free reduce
    __shared__ float  y_sh[UPB][TILE];

    const int tid  = threadIdx.x;
    const int unit = tid >> 4;          // 0..1
    const int s    = tid & 15;          // lane within unit, owns n = 4s..4s+3
    const int ug   = blockIdx.x * UPB + unit;   // (b,h) flat
    const int h    = ug % HH;

    // Parameters for this thread's 4 modes (2 packed pairs)
    const int p4 = h * (NN / 4) + s;
    float4 av = g_Are4[p4];
    float4 iv = g_Aim4[p4];
    float4 kv = g_Kre4[p4];
    float4 jv = g_Kim4[p4];

    ull aRe0 = pk2(av.x, av.y), aRe1 = pk2(av.z, av.w);
    ull aIm0 = pk2(iv.x, iv.y), aIm1 = pk2(iv.z, iv.w);
    ull nIm0 = pk2(-iv.x, -iv.y), nIm1 = pk2(-iv.z, -iv.w);
    ull kRe0 = pk2(kv.x, kv.y), kRe1 = pk2(kv.z, kv.w);
    ull kIm0 = pk2(jv.x, jv.y), kIm1 = pk2(jv.z, jv.w);

    ull zre0 = 0ull, zim0 = 0ull, zre1 = 0ull, zim1 = 0ull;
    const float Dh = Dv[h];

    const float4* u4 = (const float4*)u;
    float4*       y4 = (float4*)y;
    const size_t rowbase = (size_t)blockIdx.x * UPB;

    const int lrow = tid >> 4;   // staging row for this thread
    const int lcol = tid & 15;   // staging col (float4)

    for (int tt = 0; tt < NTILES; ++tt) {
        __syncthreads();
        // coalesced load of 2 rows x 64 timesteps (32 float4, one per thread)
        u_sh[lrow][lcol] = u4[(rowbase + lrow) * (LSEQ / 4) + tt * (TILE / 4) + lcol];
        __syncthreads();

        // ---- main recurrence: 13 f32x2 ops + 1 STS64 per step, no cross-lane deps ----
        ull* pcol = &pp_sh[unit][0][s];
        #pragma unroll 2
        for (int t4 = 0; t4 < TILE / 4; ++t4) {
            float4 uu = u_sh[unit][t4];
            #pragma unroll
            for (int j = 0; j < 4; ++j) {
                float us = (j == 0) ? uu.x : (j == 1) ? uu.y : (j == 2) ? uu.z : uu.w;
                ull uu2 = pk2(us, us);

                ull r0 = f2fma(aRe0, zre0, f2fma(nIm0, zim0, f2mul(kRe0, uu2)));
                ull i0 = f2fma(aIm0, zre0, f2fma(aRe0, zim0, f2mul(kIm0, uu2)));
                ull r1 = f2fma(aRe1, zre1, f2fma(nIm1, zim1, f2mul(kRe1, uu2)));
                ull i1 = f2fma(aIm1, zre1, f2fma(aRe1, zim1, f2mul(kIm1, uu2)));
                zre0 = r0; zim0 = i0; zre1 = r1; zim1 = i1;

                // partial y contribution of this thread's 4 modes (packed re parts)
                *pcol = f2add(r0, r1);
                pcol += 17;
            }
        }
        __syncthreads();

        // ---- deferred reduction: each thread sums 16 partials for 4 timesteps ----
        const float* ushf = (const float*)&u_sh[unit][0];
        #pragma unroll
        for (int rep = 0; rep < 4; ++rep) {
            int t = s + rep * 16;
            const ull* row = &pp_sh[unit][t][0];
            ull a0 = f2add(row[0], row[1]);
            ull a1 = f2add(row[2], row[3]);
            ull a2 = f2add(row[4], row[5]);
            ull a3 = f2add(row[6], row[7]);
            a0 = f2add(a0, f2add(row[8], row[9]));
            a1 = f2add(a1, f2add(row[10], row[11]));
            a2 = f2add(a2, f2add(row[12], row[13]));
            a3 = f2add(a3, f2add(row[14], row[15]));
            ull acc = f2add(f2add(a0, a1), f2add(a2, a3));
            float lo, hi; upk2(acc, lo, hi);
            y_sh[unit][t] = fmaf(Dh, ushf[t], lo + hi);
        }
        __syncthreads();

        // coalesced store of 2x64 output tile (32 float4)
        y4[(rowbase + lrow) * (LSEQ / 4) + tt * (TILE / 4) + lcol] =
            ((float4*)&y_sh[lrow][0])[lcol];
    }
}

extern "C" void kernel_launch(void* const* d_in, const int* in_sizes, int n_in,
                              void* d_out, int out_size) {
    const float* u    = (const float*)d_in[0];
    const float* lnr  = (const float*)d_in[1];
    const float* im   = (const float*)d_in[2];
    const float* B_re = (const float*)d_in[3];
    const float* B_im = (const float*)d_in[4];
    const float* C_re = (const float*)d_in[5];
    const float* C_im = (const float*)d_in[6];
    const float* ldt  = (const float*)d_in[7];
    const float* Dv   = (const float*)d_in[8];
    float* y = (float*)d_out;

    setup_kernel<<<(HH * NN + 255) / 256, 256>>>(lnr, im, B_re, B_im, C_re, C_im, ldt);
    ssm_scan_kernel<<<NBLOCKS, BLOCK_THREADS>>>(u, Dv, y);
}